// round 1
// baseline (speedup 1.0000x reference)
#include <cuda_runtime.h>
#include <math.h>

// ---------------------------------------------------------------------------
// GatedBlock: conv3d(72->176, k5, pad2) -> gate(144 fields) -> gaussian
// low-pass k5 stride2 -> out (4,144,16,16,16) fp32
// ---------------------------------------------------------------------------

#define B_      4
#define CI_     72
#define CO_     176
#define NS_     32
#define NSP_    (32*32*32)
#define KW9000  (CI_*125)          // per-co weight stride

// scratch (no cudaMalloc allowed)
__device__ float g_y[(size_t)B_ * CO_ * NSP_];   // raw conv output, 176 ch
__device__ float g_z[(size_t)B_ * 144 * NSP_];   // gated fields, 144 ch

// ---------------------------------------------------------------------------
// Kernel 1: direct 5^3 conv, stride1 pad2.
// Block tile: 16 co x (32x, 8y, 4z). 256 threads, thread = 8co x 8x.
// grid: (32 = 8 z-tiles * 4 y-tiles, 11 co-tiles, 4 batches)
// ---------------------------------------------------------------------------
__global__ __launch_bounds__(256, 2)
void conv_kernel(const float* __restrict__ x, const float* __restrict__ W)
{
    const int b   = blockIdx.z;
    const int co0 = blockIdx.y * 16;
    const int zt  = blockIdx.x >> 2;
    const int yt  = blockIdx.x & 3;
    const int z0  = zt * 4;
    const int y0  = yt * 8;

    const int tid = threadIdx.x;
    const int cog = tid & 1;             // 0/1 -> co offset 8*cog
    const int s   = tid >> 1;            // 0..127 spatial thread
    const int xg  = (s & 3) * 8;         // x base (0,8,16,24)
    const int yy  = (s >> 2) & 7;        // 0..7
    const int zz  = s >> 5;              // 0..3

    __shared__ float sIn[8 * 12 * 36];   // (z+4)(y+4)(x+4) input tile, 1 cin
    __shared__ float sW[125 * 16];       // [k][co]

    float acc[8][8];
#pragma unroll
    for (int c = 0; c < 8; ++c)
#pragma unroll
        for (int xx = 0; xx < 8; ++xx) acc[c][xx] = 0.f;

    const float* xb = x + (size_t)b * CI_ * NSP_;

    for (int ci = 0; ci < CI_; ++ci) {
        const float* xc = xb + (size_t)ci * NSP_;
        // ---- stage input tile (zero-padded) ----
        for (int i = tid; i < 8 * 12 * 36; i += 256) {
            int xi = i % 36;
            int t  = i / 36;
            int yi = t % 12;
            int zi = t / 12;
            int gx = xi - 2, gy = y0 + yi - 2, gz = z0 + zi - 2;
            float v = 0.f;
            if ((unsigned)gx < 32u && (unsigned)gy < 32u && (unsigned)gz < 32u)
                v = xc[(gz * 32 + gy) * 32 + gx];
            sIn[i] = v;
        }
        // ---- stage weights: sW[k][co] ----
        const float* wb = W + ci * 125;
        for (int i = tid; i < 2000; i += 256) {
            int co = i & 15;
            int k  = i >> 4;
            sW[i] = wb[(size_t)(co0 + co) * KW9000 + k];
        }
        __syncthreads();

        // ---- compute ----
#pragma unroll 1
        for (int kd = 0; kd < 5; ++kd) {
#pragma unroll 1
            for (int kh = 0; kh < 5; ++kh) {
                const float4* ir =
                    (const float4*)&sIn[((zz + kd) * 12 + (yy + kh)) * 36 + xg];
                float4 a0 = ir[0], a1 = ir[1], a2 = ir[2];
                float r[12] = {a0.x, a0.y, a0.z, a0.w,
                               a1.x, a1.y, a1.z, a1.w,
                               a2.x, a2.y, a2.z, a2.w};
                const float4* wp =
                    (const float4*)&sW[(kd * 5 + kh) * 5 * 16 + cog * 8];
#pragma unroll
                for (int kw = 0; kw < 5; ++kw) {
                    float4 w0 = wp[kw * 4];
                    float4 w1 = wp[kw * 4 + 1];
                    float wv[8] = {w0.x, w0.y, w0.z, w0.w,
                                   w1.x, w1.y, w1.z, w1.w};
#pragma unroll
                    for (int c = 0; c < 8; ++c)
#pragma unroll
                        for (int xx = 0; xx < 8; ++xx)
                            acc[c][xx] += wv[c] * r[kw + xx];
                }
            }
        }
        __syncthreads();
    }

    // ---- write raw conv output ----
#pragma unroll
    for (int c = 0; c < 8; ++c) {
        int co = co0 + cog * 8 + c;
        float* yo = g_y +
            ((((size_t)b * CO_ + co) * 32 + (z0 + zz)) * 32 + (y0 + yy)) * 32 + xg;
        *(float4*)(yo)     = make_float4(acc[c][0], acc[c][1], acc[c][2], acc[c][3]);
        *(float4*)(yo + 4) = make_float4(acc[c][4], acc[c][5], acc[c][6], acc[c][7]);
    }
}

// ---------------------------------------------------------------------------
// Kernel 2: gating. z[c] = relu(y[c]+sb[c]) for c<16,
// else y[c] * sigmoid(y[gate_ch]+gb[gi]).
// ---------------------------------------------------------------------------
__global__ void gate_kernel(const float* __restrict__ sb,
                            const float* __restrict__ gb)
{
    size_t i = (size_t)blockIdx.x * 256 + threadIdx.x;
    const size_t total = (size_t)B_ * 144 * NSP_;
    if (i >= total) return;
    int sp = (int)(i & (NSP_ - 1));
    int t  = (int)(i >> 15);
    int c  = t % 144;
    int b  = t / 144;
    const float* yb = g_y + (size_t)b * CO_ * NSP_;
    float v = yb[(size_t)c * NSP_ + sp];
    float out;
    if (c < 16) {
        out = fmaxf(v + sb[c], 0.f);
    } else {
        int gi = (c < 64) ? ((c - 16) / 3) : (16 + (c - 64) / 5);
        float gv = yb[(size_t)(144 + gi) * NSP_ + sp];
        float sg = 1.f / (1.f + expf(-(gv + gb[gi])));
        out = v * sg;
    }
    g_z[i] = out;
}

// ---------------------------------------------------------------------------
// Kernel 3: depthwise 5^3 gaussian, stride2, pad2 -> (16,16,16).
// Block: one (b,c) and 2 output z-planes. grid (8, 144, 4).
// ---------------------------------------------------------------------------
__global__ __launch_bounds__(256)
void lowpass_kernel(float* __restrict__ out)
{
    const int zt = blockIdx.x;        // 0..7 -> zo0 = 2*zt
    const int c  = blockIdx.y;
    const int b  = blockIdx.z;
    const int tid = threadIdx.x;

    __shared__ float sZ[7 * 35 * 35]; // 8575 floats
    __shared__ float sWg[125];

    // gaussian weights, computed in double to match the fp64 reference
    if (tid < 125) {
        int kw = tid % 5, t = tid / 5;
        int kh = t % 5,  kd = t / 5;
        double g[5], s = 0.0;
#pragma unroll
        for (int r = 0; r < 5; ++r) {
            double d = (double)(r - 2);
            g[r] = exp(-d * d / 1.5);   // 2*sigma^2 = 1.5, sigma=0.5*sqrt(3)
            s += g[r];
        }
        sWg[tid] = (float)(g[kd] * g[kh] * g[kw] / (s * s * s));
    }

    const int zo0 = 2 * zt;
    const int zi0 = 2 * zo0 - 2;
    const float* zc = g_z + (size_t)(b * 144 + c) * NSP_;

    for (int i = tid; i < 7 * 35 * 35; i += 256) {
        int xi = i % 35;
        int t  = i / 35;
        int yi = t % 35;
        int zi = t / 35;
        int gx = xi - 2, gy = yi - 2, gz = zi0 + zi;
        float v = 0.f;
        if ((unsigned)gx < 32u && (unsigned)gy < 32u && (unsigned)gz < 32u)
            v = zc[(gz * 32 + gy) * 32 + gx];
        sZ[i] = v;
    }
    __syncthreads();

    const int xo = tid & 15;
    const int yo = tid >> 4;
#pragma unroll
    for (int dz = 0; dz < 2; ++dz) {
        float sum = 0.f;
#pragma unroll
        for (int kd = 0; kd < 5; ++kd)
#pragma unroll
            for (int kh = 0; kh < 5; ++kh)
#pragma unroll
                for (int kw = 0; kw < 5; ++kw)
                    sum += sWg[(kd * 5 + kh) * 5 + kw] *
                           sZ[((2 * dz + kd) * 35 + (2 * yo + kh)) * 35 +
                              2 * xo + kw];
        out[((size_t)(b * 144 + c) * 16 + (zo0 + dz)) * 256 + yo * 16 + xo] = sum;
    }
}

// ---------------------------------------------------------------------------
extern "C" void kernel_launch(void* const* d_in, const int* in_sizes, int n_in,
                              void* d_out, int out_size)
{
    const float* x  = (const float*)d_in[0];   // (4,72,32,32,32)
    const float* W  = (const float*)d_in[1];   // (176,72,5,5,5)
    const float* sb = (const float*)d_in[2];   // (16,)
    const float* gb = (const float*)d_in[3];   // (32,)
    float* out = (float*)d_out;                // (4,144,16,16,16)

    dim3 cgrid(32, 11, B_);                    // 8 z-tiles * 4 y-tiles, 11 co, 4 b
    conv_kernel<<<cgrid, 256>>>(x, W);

    size_t total = (size_t)B_ * 144 * NSP_;
    gate_kernel<<<(unsigned)((total + 255) / 256), 256>>>(sb, gb);

    dim3 lgrid(8, 144, B_);
    lowpass_kernel<<<lgrid, 256>>>(out);
}

// round 2
// speedup vs baseline: 1.1353x; 1.1353x over previous
#include <cuda_runtime.h>
#include <math.h>

// ---------------------------------------------------------------------------
// GatedBlock: conv3d(72->176, k5, pad2) -> gate(144 fields) -> gaussian
// low-pass k5 stride2 -> out (4,144,16,16,16) fp32
// Round 2: packed f32x2 FFMA2 conv + cp.async double buffering.
// ---------------------------------------------------------------------------

#define B_      4
#define CI_     72
#define CO_     176
#define NSP_    (32*32*32)
#define KW_STR  (CI_*125)          // per-co weight stride

__device__ float g_y[(size_t)B_ * CO_ * NSP_];   // raw conv output, 176 ch
__device__ float g_z[(size_t)B_ * 144 * NSP_];   // gated fields, 144 ch

#define PACK2(d, s)  asm("mov.b64 %0, {%1, %1};" : "=l"(d) : "r"(s))
#define UNPK2(lo, hi, s) asm("mov.b64 {%0, %1}, %2;" : "=r"(lo), "=r"(hi) : "l"(s))
#define FMA2(acc, a, b) asm("fma.rn.f32x2 %0, %1, %2, %0;" : "+l"(acc) : "l"(a), "l"(b))
#define CPA8(dst, src)  asm volatile("cp.async.ca.shared.global [%0], [%1], 8;" :: "r"(dst), "l"(src))
#define CPA4(dst, src)  asm volatile("cp.async.ca.shared.global [%0], [%1], 4;" :: "r"(dst), "l"(src))
#define CPC()  asm volatile("cp.async.commit_group;")
#define CPW0() asm volatile("cp.async.wait_group 0;")

// ---------------------------------------------------------------------------
// Kernel 1: direct 5^3 conv, stride1 pad2.
// Block tile: 16 co x (32x, 8y, 4z). 256 threads; thread = 8co x 8x,
// accumulators packed as f32x2 over co-pairs.
// grid: (32 = 8 z-tiles * 4 y-tiles, 11 co-tiles, 4 batches)
// ---------------------------------------------------------------------------
__global__ __launch_bounds__(256, 2)
void conv_kernel(const float* __restrict__ x, const float* __restrict__ W)
{
    const int b   = blockIdx.z;
    const int co0 = blockIdx.y * 16;
    const int z0  = (blockIdx.x >> 2) * 4;
    const int y0  = (blockIdx.x & 3) * 8;

    const int tid = threadIdx.x;
    const int cog = tid & 1;             // 0/1 -> co offset 8*cog
    const int s   = tid >> 1;            // 0..127 spatial thread
    const int xg  = (s & 3) * 8;         // x base (0,8,16,24)
    const int yy  = (s >> 2) & 7;        // 0..7
    const int zz  = s >> 5;              // 0..3

    __shared__ float sIn[2][8 * 12 * 36];   // (z+4)(y+4)(x+4) input tile
    __shared__ float sW[2][125 * 16];       // [k][co]

    // zero both input buffers once: halo cells stay 0 forever,
    // interior is overwritten by cp.async each iteration.
    for (int i = tid; i < 2 * 3456; i += 256) ((float*)sIn)[i] = 0.f;
    __syncthreads();

    const float* xb = x + (size_t)b * CI_ * NSP_;

    auto stage = [&](int ci, int buf) {
        const float* xc = xb + (size_t)ci * NSP_;
        unsigned sin_b = (unsigned)__cvta_generic_to_shared(&sIn[buf][0]);
        // 96 (z,y) rows x 16 chunks of 8B (cols 2..33)
        for (int it = tid; it < 96 * 16; it += 256) {
            int ck  = it & 15;
            int row = it >> 4;
            int yi = row % 12, zi = row / 12;
            int gy = y0 + yi - 2, gz = z0 + zi - 2;
            if ((unsigned)gy < 32u && (unsigned)gz < 32u)
                CPA8(sin_b + (row * 36 + 2 + ck * 2) * 4,
                     xc + (gz * 32 + gy) * 32 + ck * 2);
        }
        unsigned sw_b = (unsigned)__cvta_generic_to_shared(&sW[buf][0]);
        const float* wb = W + ci * 125;
        for (int i = tid; i < 2000; i += 256) {
            int co = i & 15;
            int k  = i >> 4;
            CPA4(sw_b + i * 4, wb + (size_t)(co0 + co) * KW_STR + k);
        }
    };

    stage(0, 0); CPC();

    unsigned long long acc[4][8];
#pragma unroll
    for (int p = 0; p < 4; ++p)
#pragma unroll
        for (int xx = 0; xx < 8; ++xx) acc[p][xx] = 0ull;

    for (int ci = 0; ci < CI_; ++ci) {
        const int buf = ci & 1;
        CPW0();
        __syncthreads();
        if (ci + 1 < CI_) { stage(ci + 1, buf ^ 1); CPC(); }

        const float* sInb = sIn[buf];
        const float* sWb  = sW[buf];

#pragma unroll 1
        for (int kd = 0; kd < 5; ++kd) {
#pragma unroll 1
            for (int kh = 0; kh < 5; ++kh) {
                const float4* ir =
                    (const float4*)&sInb[((zz + kd) * 12 + (yy + kh)) * 36 + xg];
                float4 a0 = ir[0], a1 = ir[1], a2 = ir[2];
                unsigned long long rs[12];
                PACK2(rs[0],  __float_as_uint(a0.x));
                PACK2(rs[1],  __float_as_uint(a0.y));
                PACK2(rs[2],  __float_as_uint(a0.z));
                PACK2(rs[3],  __float_as_uint(a0.w));
                PACK2(rs[4],  __float_as_uint(a1.x));
                PACK2(rs[5],  __float_as_uint(a1.y));
                PACK2(rs[6],  __float_as_uint(a1.z));
                PACK2(rs[7],  __float_as_uint(a1.w));
                PACK2(rs[8],  __float_as_uint(a2.x));
                PACK2(rs[9],  __float_as_uint(a2.y));
                PACK2(rs[10], __float_as_uint(a2.z));
                PACK2(rs[11], __float_as_uint(a2.w));

                const int kb = (kd * 5 + kh) * 5;
#pragma unroll
                for (int kw = 0; kw < 5; ++kw) {
                    // co-pairs come packed straight from smem (co contiguous)
                    const ulonglong2* wp =
                        (const ulonglong2*)&sWb[(kb + kw) * 16 + cog * 8];
                    ulonglong2 wA = wp[0], wB = wp[1];
                    unsigned long long w4[4] = {wA.x, wA.y, wB.x, wB.y};
#pragma unroll
                    for (int p = 0; p < 4; ++p)
#pragma unroll
                        for (int xx = 0; xx < 8; ++xx)
                            FMA2(acc[p][xx], w4[p], rs[kw + xx]);
                }
            }
        }
    }

    // ---- write raw conv output (unpack co-pairs) ----
#pragma unroll
    for (int p = 0; p < 4; ++p) {
        unsigned lo[8], hi[8];
#pragma unroll
        for (int xx = 0; xx < 8; ++xx) UNPK2(lo[xx], hi[xx], acc[p][xx]);
        const int coL = co0 + cog * 8 + 2 * p;
        float* yo = g_y +
            ((((size_t)b * CO_ + coL) * 32 + (z0 + zz)) * 32 + (y0 + yy)) * 32 + xg;
        ((uint4*)yo)[0] = make_uint4(lo[0], lo[1], lo[2], lo[3]);
        ((uint4*)yo)[1] = make_uint4(lo[4], lo[5], lo[6], lo[7]);
        float* yo1 = yo + NSP_;   // coL+1
        ((uint4*)yo1)[0] = make_uint4(hi[0], hi[1], hi[2], hi[3]);
        ((uint4*)yo1)[1] = make_uint4(hi[4], hi[5], hi[6], hi[7]);
    }
}

// ---------------------------------------------------------------------------
// Kernel 2: gating. z[c] = relu(y[c]+sb[c]) for c<16,
// else y[c] * sigmoid(y[gate_ch]+gb[gi]).
// ---------------------------------------------------------------------------
__global__ void gate_kernel(const float* __restrict__ sb,
                            const float* __restrict__ gb)
{
    size_t i = (size_t)blockIdx.x * 256 + threadIdx.x;
    const size_t total = (size_t)B_ * 144 * NSP_;
    if (i >= total) return;
    int sp = (int)(i & (NSP_ - 1));
    int t  = (int)(i >> 15);
    int c  = t % 144;
    int b  = t / 144;
    const float* yb = g_y + (size_t)b * CO_ * NSP_;
    float v = yb[(size_t)c * NSP_ + sp];
    float out;
    if (c < 16) {
        out = fmaxf(v + sb[c], 0.f);
    } else {
        int gi = (c < 64) ? ((c - 16) / 3) : (16 + (c - 64) / 5);
        float gv = yb[(size_t)(144 + gi) * NSP_ + sp];
        float sg = 1.f / (1.f + expf(-(gv + gb[gi])));
        out = v * sg;
    }
    g_z[i] = out;
}

// ---------------------------------------------------------------------------
// Kernel 3: depthwise 5^3 gaussian, stride2, pad2 -> (16,16,16).
// Block: one (b,c) and 2 output z-planes. grid (8, 144, 4).
// ---------------------------------------------------------------------------
__global__ __launch_bounds__(256)
void lowpass_kernel(float* __restrict__ out)
{
    const int zt = blockIdx.x;        // 0..7 -> zo0 = 2*zt
    const int c  = blockIdx.y;
    const int b  = blockIdx.z;
    const int tid = threadIdx.x;

    __shared__ float sZ[7 * 35 * 35]; // 8575 floats
    __shared__ float sWg[125];

    // gaussian weights, computed in double to match the fp64 reference
    if (tid < 125) {
        int kw = tid % 5, t = tid / 5;
        int kh = t % 5,  kd = t / 5;
        double g[5], s = 0.0;
#pragma unroll
        for (int r = 0; r < 5; ++r) {
            double d = (double)(r - 2);
            g[r] = exp(-d * d / 1.5);   // 2*sigma^2 = 1.5, sigma=0.5*sqrt(3)
            s += g[r];
        }
        sWg[tid] = (float)(g[kd] * g[kh] * g[kw] / (s * s * s));
    }

    const int zo0 = 2 * zt;
    const int zi0 = 2 * zo0 - 2;
    const float* zc = g_z + (size_t)(b * 144 + c) * NSP_;

    for (int i = tid; i < 7 * 35 * 35; i += 256) {
        int xi = i % 35;
        int t  = i / 35;
        int yi = t % 35;
        int zi = t / 35;
        int gx = xi - 2, gy = yi - 2, gz = zi0 + zi;
        float v = 0.f;
        if ((unsigned)gx < 32u && (unsigned)gy < 32u && (unsigned)gz < 32u)
            v = zc[(gz * 32 + gy) * 32 + gx];
        sZ[i] = v;
    }
    __syncthreads();

    const int xo = tid & 15;
    const int yo = tid >> 4;
#pragma unroll
    for (int dz = 0; dz < 2; ++dz) {
        float sum = 0.f;
#pragma unroll
        for (int kd = 0; kd < 5; ++kd)
#pragma unroll
            for (int kh = 0; kh < 5; ++kh)
#pragma unroll
                for (int kw = 0; kw < 5; ++kw)
                    sum += sWg[(kd * 5 + kh) * 5 + kw] *
                           sZ[((2 * dz + kd) * 35 + (2 * yo + kh)) * 35 +
                              2 * xo + kw];
        out[((size_t)(b * 144 + c) * 16 + (zo0 + dz)) * 256 + yo * 16 + xo] = sum;
    }
}

// ---------------------------------------------------------------------------
extern "C" void kernel_launch(void* const* d_in, const int* in_sizes, int n_in,
                              void* d_out, int out_size)
{
    const float* x  = (const float*)d_in[0];   // (4,72,32,32,32)
    const float* W  = (const float*)d_in[1];   // (176,72,5,5,5)
    const float* sb = (const float*)d_in[2];   // (16,)
    const float* gb = (const float*)d_in[3];   // (32,)
    float* out = (float*)d_out;                // (4,144,16,16,16)

    dim3 cgrid(32, 11, B_);                    // 8 z * 4 y tiles, 11 co, 4 b
    conv_kernel<<<cgrid, 256>>>(x, W);

    size_t total = (size_t)B_ * 144 * NSP_;
    gate_kernel<<<(unsigned)((total + 255) / 256), 256>>>(sb, gb);

    dim3 lgrid(8, 144, B_);
    lowpass_kernel<<<lgrid, 256>>>(out);
}

// round 4
// speedup vs baseline: 1.9600x; 1.7264x over previous
#include <cuda_runtime.h>
#include <cuda_bf16.h>
#include <math.h>
#include <stdint.h>

// ---------------------------------------------------------------------------
// GatedBlock via mma.sync bf16 implicit GEMM (hi/lo 3-term for fp32 accuracy)
//   conv3d(72->176, k5, pad2)  ==>  D[M=128 spatial, N=176 co], K = 72*128
//   gate fused into the GEMM epilogue, then depthwise gaussian stride-2.
// NOTE: tcgen05 is NOT usable (harness compiles at compute_103, no 'a').
// ---------------------------------------------------------------------------

#define B_      4
#define CI_     72
#define CO_     176
#define NSP_    (32*32*32)
#define NCH_    144

#define KC_     64            // K per chunk
#define NCHUNK_ 144           // 72*128 / 64
#define A_TILE  16384         // 128 rows x 64 bf16 x 2B
#define B_TILE  22528         // 176 rows x 64 bf16 x 2B

__device__ float g_z[(size_t)B_ * NCH_ * NSP_];
__device__ __nv_bfloat16 g_wprep[(size_t)NCHUNK_ * 2 * CO_ * KC_];  // pre-swizzled

// ---- smem byte offsets (dynamic smem) ----
#define SA_OFF    0            // A: [buf][hi,lo]  4 * 16384 = 65536
#define SB_OFF    65536        // B: [buf][hi,lo]  4 * 22528 = 90112 -> 155648
#define SX_OFF    155648       // xs: 1584 floats (incl 144-zero tail)
#define XS_FLOATS 1584
#define ST_OFF    161984       // tapoff table: 128 ints
#define SSB_OFF   162496       // scalar_bias 16 f
#define SGB_OFF   162560       // gate_bias 32 f
#define SMEM_TOTAL 162816

// ---------------- helpers ----------------
__device__ __forceinline__ uint32_t smem_u32(const void* p){
    uint32_t a;
    asm("{ .reg .u64 t; cvta.to.shared.u64 t, %1; cvt.u32.u64 %0, t; }"
        : "=r"(a) : "l"(p));
    return a;
}
__device__ __forceinline__ uint32_t swz(uint32_t o){
    return o ^ (((o >> 7) & 7u) << 4);
}

#define CPA16(d,s) asm volatile("cp.async.cg.shared.global [%0], [%1], 16;" :: "r"(d), "l"(s))
#define CPA8(d,s)  asm volatile("cp.async.ca.shared.global [%0], [%1], 8;"  :: "r"(d), "l"(s))
#define CPC()      asm volatile("cp.async.commit_group;")
#define CPW0()     asm volatile("cp.async.wait_group 0;")

#define LDM4(r, a) \
    asm volatile("ldmatrix.sync.aligned.m8n8.x4.shared.b16 {%0,%1,%2,%3}, [%4];" \
        : "=r"((r)[0]),"=r"((r)[1]),"=r"((r)[2]),"=r"((r)[3]) : "r"(a))
#define LDM2(r, a) \
    asm volatile("ldmatrix.sync.aligned.m8n8.x2.shared.b16 {%0,%1}, [%2];" \
        : "=r"((r)[0]),"=r"((r)[1]) : "r"(a))

#define MMA16816(d, a, b0v, b1v) \
    asm volatile("mma.sync.aligned.m16n8k16.row.col.f32.bf16.bf16.f32 " \
        "{%0,%1,%2,%3}, {%4,%5,%6,%7}, {%8,%9}, {%0,%1,%2,%3};" \
        : "+f"((d)[0]),"+f"((d)[1]),"+f"((d)[2]),"+f"((d)[3]) \
        : "r"((a)[0]),"r"((a)[1]),"r"((a)[2]),"r"((a)[3]), "r"(b0v), "r"(b1v))

// ---------------------------------------------------------------------------
// Weight prep: reorder to K=(ci*128+tap), split bf16 hi/lo, pre-apply the
// XOR swizzle so the main kernel can cp.async the tiles linearly.
// ---------------------------------------------------------------------------
__global__ void prep_kernel(const float* __restrict__ W)
{
    int e = blockIdx.x * 256 + threadIdx.x;   // 144*176*64 = 1,622,016 exact
    int col   = e & 63;
    int row   = (e >> 6) % CO_;
    int chunk = e / (CO_ * KC_);
    int k  = chunk * KC_ + col;
    int ci = k >> 7;
    int tap = k & 127;
    float v = (tap < 125) ? W[((size_t)row * CI_ + ci) * 125 + tap] : 0.f;
    __nv_bfloat16 hi = __float2bfloat16(v);
    __nv_bfloat16 lo = __float2bfloat16(v - __bfloat162float(hi));
    uint32_t off = (uint32_t)(row * 128 + col * 2);
    uint32_t sw  = off ^ ((uint32_t)(row & 7) << 4);
    size_t base = (size_t)chunk * 2 * (CO_ * KC_);
    g_wprep[base + (sw >> 1)]             = hi;
    g_wprep[base + CO_ * KC_ + (sw >> 1)] = lo;
}

// ---------------------------------------------------------------------------
// Main kernel: implicit GEMM + fused gate epilogue.
// grid (8 y-tiles, 32 z, 4 b), 256 threads. M-tile = 4y x 32x at fixed z.
// warps: 4M x 2N, warp tile M=32, N=88.
// ---------------------------------------------------------------------------
__global__ __launch_bounds__(256)
void conv_mma_kernel(const float* __restrict__ x,
                     const float* __restrict__ sbg, const float* __restrict__ gbg)
{
    extern __shared__ unsigned char smem[];
    const uint32_t smb = smem_u32(smem);

    const int tid = threadIdx.x;
    const int wid = tid >> 5;
    const int lid = tid & 31;
    const int b  = blockIdx.z;
    const int z0 = blockIdx.y;
    const int y0 = blockIdx.x * 4;

    // builder role
    const int byy = wid & 3, bkh = wid >> 2, bxx = lid;
    // mma role
    const int m0 = (wid >> 1) * 32;
    const int n0 = (wid & 1) * 88;

    float* xs     = (float*)(smem + SX_OFF);
    int*   tapoff = (int*)(smem + ST_OFF);
    float* sS     = (float*)(smem + SSB_OFF);
    float* sG     = (float*)(smem + SGB_OFF);

    for (int i = tid; i < XS_FLOATS; i += 256) xs[i] = 0.f;
    if (tid < 128) {
        int tap = tid;
        int kd = tap / 25, r = tap % 25;
        int kh = r / 5, kw = r % 5;
        tapoff[tid] = (tap < 125) ? (kd * 8 + kh) * 36 + kw : 1440;
    }
    if (tid < 16) sS[tid] = sbg[tid];
    if (tid < 32) sG[tid] = gbg[tid];
    __syncthreads();

    const float* xb = x + (size_t)b * CI_ * NSP_;

    auto stage_x = [&](int ci) {
        const float* xc = xb + (size_t)ci * NSP_;
        for (int it = tid; it < 640; it += 256) {
            int ck = it & 15;
            int row = it >> 4;           // zi*8 + yi
            int yi = row & 7, zi = row >> 3;
            int gy = y0 + yi - 2, gz = z0 + zi - 2;
            if ((unsigned)gy < 32u && (unsigned)gz < 32u)
                CPA8(smb + SX_OFF + (uint32_t)(row * 36 + 2 + ck * 2) * 4,
                     xc + ((gz * 32 + gy) * 32 + ck * 2));
        }
    };
    auto stage_B = [&](int n, int nb) {
        const char* src = (const char*)g_wprep + (size_t)n * (2 * B_TILE);
        uint32_t dst = smb + SB_OFF + nb * (2 * B_TILE);
        for (int i = tid; i < (2 * B_TILE) / 16; i += 256)
            CPA16(dst + i * 16, src + i * 16);
    };
    auto build_A = [&](int n, int nb) {
        char* Ah = (char*)smem + SA_OFF + nb * (2 * A_TILE);
        char* Al = Ah + A_TILE;
        const int tb  = (n & 1) * 64;
        const int lin = byy * 36 + bxx;
        const int m   = byy * 32 + bxx;
        const uint32_t mx = (uint32_t)(m & 7) << 4;
#pragma unroll 4
        for (int j = 0; j < 16; ++j) {
            int k0 = bkh * 32 + 2 * j;
            float v0 = xs[tapoff[tb + k0]     + lin];
            float v1 = xs[tapoff[tb + k0 + 1] + lin];
            __nv_bfloat16 h0 = __float2bfloat16(v0);
            __nv_bfloat16 h1 = __float2bfloat16(v1);
            __nv_bfloat16 l0 = __float2bfloat16(v0 - __bfloat162float(h0));
            __nv_bfloat16 l1 = __float2bfloat16(v1 - __bfloat162float(h1));
            uint32_t hp = (uint32_t)__bfloat16_as_ushort(h0) |
                          ((uint32_t)__bfloat16_as_ushort(h1) << 16);
            uint32_t lp = (uint32_t)__bfloat16_as_ushort(l0) |
                          ((uint32_t)__bfloat16_as_ushort(l1) << 16);
            uint32_t sw = ((uint32_t)(m * 128 + k0 * 2)) ^ mx;
            *(uint32_t*)(Ah + sw) = hp;
            *(uint32_t*)(Al + sw) = lp;
        }
    };

    // lane-invariant ldmatrix offsets
    const uint32_t aLane  = (uint32_t)((lid & 15) * 128 + ((lid & 16) ? 16 : 0));
    const uint32_t bLane4 = (uint32_t)((((lid & 7) + ((lid & 16) ? 8 : 0)) * 128) +
                                       ((lid & 8) ? 16 : 0));
    const uint32_t bLane2 = (uint32_t)((lid & 7) * 128 + ((lid & 8) ? 16 : 0));

    float acc[2][11][4];
#pragma unroll
    for (int mi = 0; mi < 2; ++mi)
#pragma unroll
        for (int ni = 0; ni < 11; ++ni)
#pragma unroll
            for (int r = 0; r < 4; ++r) acc[mi][ni][r] = 0.f;

    // ---- prologue ----
    stage_B(0, 0);
    stage_x(0);
    CPC(); CPW0();
    __syncthreads();
    build_A(0, 0);
    __syncthreads();

    for (int c = 0; c < NCHUNK_; ++c) {
        const int bsel = c & 1;
        if (c + 1 < NCHUNK_) {
            stage_B(c + 1, bsel ^ 1);
            if (((c + 1) & 1) == 0) stage_x((c + 1) >> 1);
            CPC();
        }

        const uint32_t AhB = smb + SA_OFF + bsel * (2 * A_TILE);
        const uint32_t AlB = AhB + A_TILE;
        const uint32_t BhB = smb + SB_OFF + bsel * (2 * B_TILE);
        const uint32_t BlB = BhB + B_TILE;

#pragma unroll
        for (int ks = 0; ks < 4; ++ks) {
            const uint32_t kso = (uint32_t)ks * 32;
            uint32_t ah[2][4], al[2][4];
            LDM4(ah[0], AhB + swz((uint32_t)(m0      * 128) + kso + aLane));
            LDM4(ah[1], AhB + swz((uint32_t)((m0+16) * 128) + kso + aLane));
            LDM4(al[0], AlB + swz((uint32_t)(m0      * 128) + kso + aLane));
            LDM4(al[1], AlB + swz((uint32_t)((m0+16) * 128) + kso + aLane));
#pragma unroll
            for (int nip = 0; nip < 5; ++nip) {
                uint32_t bh[4], bl[4];
                const uint32_t bo =
                    swz((uint32_t)((n0 + nip * 16) * 128) + kso + bLane4);
                LDM4(bh, BhB + bo);
                LDM4(bl, BlB + bo);
#pragma unroll
                for (int sub = 0; sub < 2; ++sub) {
                    const int ni = nip * 2 + sub;
                    MMA16816(acc[0][ni], ah[0], bh[sub*2], bh[sub*2+1]);
                    MMA16816(acc[1][ni], ah[1], bh[sub*2], bh[sub*2+1]);
                    MMA16816(acc[0][ni], al[0], bh[sub*2], bh[sub*2+1]);
                    MMA16816(acc[1][ni], al[1], bh[sub*2], bh[sub*2+1]);
                    MMA16816(acc[0][ni], ah[0], bl[sub*2], bl[sub*2+1]);
                    MMA16816(acc[1][ni], ah[1], bl[sub*2], bl[sub*2+1]);
                }
            }
            {   // n-group 10 (cols 80..87)
                uint32_t bh[2], bl[2];
                const uint32_t bo =
                    swz((uint32_t)((n0 + 80) * 128) + kso + bLane2);
                LDM2(bh, BhB + bo);
                LDM2(bl, BlB + bo);
                MMA16816(acc[0][10], ah[0], bh[0], bh[1]);
                MMA16816(acc[1][10], ah[1], bh[0], bh[1]);
                MMA16816(acc[0][10], al[0], bh[0], bh[1]);
                MMA16816(acc[1][10], al[1], bh[0], bh[1]);
                MMA16816(acc[0][10], ah[0], bl[0], bl[1]);
                MMA16816(acc[1][10], ah[1], bl[0], bl[1]);
            }
        }

        if (c + 1 < NCHUNK_) {
            CPW0();
            __syncthreads();
            build_A(c + 1, bsel ^ 1);
        }
        __syncthreads();
    }

    // ---- epilogue: accums -> smem, sigmoid gates, gated write to g_z ----
    float* sD = (float*)smem;   // [176][132] floats = 92928B, reuses tile smem
#pragma unroll
    for (int mi = 0; mi < 2; ++mi)
#pragma unroll
        for (int ni = 0; ni < 11; ++ni)
#pragma unroll
            for (int r = 0; r < 4; ++r) {
                int m  = m0 + mi * 16 + (lid >> 2) + ((r & 2) ? 8 : 0);
                int cc = n0 + ni * 8 + (lid & 3) * 2 + (r & 1);
                sD[cc * 132 + m] = acc[mi][ni][r];
            }
    __syncthreads();

    for (int i = tid; i < 32 * 128; i += 256) {
        int gi = i >> 7, mm = i & 127;
        int ad = (144 + gi) * 132 + mm;
        sD[ad] = 1.f / (1.f + expf(-(sD[ad] + sG[gi])));
    }
    __syncthreads();

    float* zb = g_z + (size_t)b * NCH_ * NSP_ + (size_t)z0 * 1024 + y0 * 32;
    for (int i = tid; i < 144 * 128; i += 256) {
        int cc = i >> 7, mm = i & 127;
        float v = sD[cc * 132 + mm];
        float o;
        if (cc < 16) o = fmaxf(v + sS[cc], 0.f);
        else {
            int gi = (cc < 64) ? (cc - 16) / 3 : 16 + (cc - 64) / 5;
            o = v * sD[(144 + gi) * 132 + mm];
        }
        zb[(size_t)cc * NSP_ + mm] = o;
    }
}

// ---------------------------------------------------------------------------
// Depthwise 5^3 gaussian, stride2, pad2 -> (16,16,16). grid (8, 144, 4).
// ---------------------------------------------------------------------------
__global__ __launch_bounds__(256)
void lowpass_kernel(float* __restrict__ out)
{
    const int zt = blockIdx.x;
    const int c  = blockIdx.y;
    const int b  = blockIdx.z;
    const int tid = threadIdx.x;

    __shared__ float sZ[7 * 35 * 35];
    __shared__ float sWg[125];

    if (tid < 125) {
        int kw = tid % 5, t = tid / 5;
        int kh = t % 5,  kd = t / 5;
        double g[5], s = 0.0;
#pragma unroll
        for (int r = 0; r < 5; ++r) {
            double d = (double)(r - 2);
            g[r] = exp(-d * d / 1.5);
            s += g[r];
        }
        sWg[tid] = (float)(g[kd] * g[kh] * g[kw] / (s * s * s));
    }

    const int zo0 = 2 * zt;
    const int zi0 = 2 * zo0 - 2;
    const float* zc = g_z + (size_t)(b * NCH_ + c) * NSP_;

    for (int i = tid; i < 7 * 35 * 35; i += 256) {
        int xi = i % 35;
        int t  = i / 35;
        int yi = t % 35;
        int zi = t / 35;
        int gx = xi - 2, gy = yi - 2, gz = zi0 + zi;
        float v = 0.f;
        if ((unsigned)gx < 32u && (unsigned)gy < 32u && (unsigned)gz < 32u)
            v = zc[(gz * 32 + gy) * 32 + gx];
        sZ[i] = v;
    }
    __syncthreads();

    const int xo = tid & 15;
    const int yo = tid >> 4;
#pragma unroll
    for (int dz = 0; dz < 2; ++dz) {
        float sum = 0.f;
#pragma unroll
        for (int kd = 0; kd < 5; ++kd)
#pragma unroll
            for (int kh = 0; kh < 5; ++kh)
#pragma unroll
                for (int kw = 0; kw < 5; ++kw)
                    sum += sWg[(kd * 5 + kh) * 5 + kw] *
                           sZ[((2 * dz + kd) * 35 + (2 * yo + kh)) * 35 +
                              2 * xo + kw];
        out[((size_t)(b * NCH_ + c) * 16 + (zo0 + dz)) * 256 + yo * 16 + xo] = sum;
    }
}

// ---------------------------------------------------------------------------
extern "C" void kernel_launch(void* const* d_in, const int* in_sizes, int n_in,
                              void* d_out, int out_size)
{
    const float* x  = (const float*)d_in[0];   // (4,72,32,32,32)
    const float* W  = (const float*)d_in[1];   // (176,72,5,5,5)
    const float* sb = (const float*)d_in[2];   // (16,)
    const float* gb = (const float*)d_in[3];   // (32,)
    float* out = (float*)d_out;                // (4,144,16,16,16)

    cudaFuncSetAttribute(conv_mma_kernel,
                         cudaFuncAttributeMaxDynamicSharedMemorySize, SMEM_TOTAL);

    prep_kernel<<<6336, 256>>>(W);
    conv_mma_kernel<<<dim3(8, 32, B_), 256, SMEM_TOTAL>>>(x, sb, gb);
    lowpass_kernel<<<dim3(8, NCH_, B_), 256>>>(out);
}

// round 5
// speedup vs baseline: 2.1878x; 1.1162x over previous
#include <cuda_runtime.h>
#include <cuda_bf16.h>
#include <math.h>
#include <stdint.h>

// ---------------------------------------------------------------------------
// GatedBlock via mma.sync bf16 implicit GEMM (hi/lo 3-term for fp32 accuracy)
//   conv3d(72->176, k5, pad2)  ==>  D[M=128 spatial, N=176 co], K = 72*128
//   gate fused into the GEMM epilogue, then depthwise gaussian stride-2.
// Round 5: 512 threads / 16 warps (warp tile 16x88) for MMA/build overlap.
// ---------------------------------------------------------------------------

#define B_      4
#define CI_     72
#define CO_     176
#define NSP_    (32*32*32)
#define NCH_    144

#define KC_     64            // K per chunk
#define NCHUNK_ 144           // 72*128 / 64
#define A_TILE  16384         // 128 rows x 64 bf16 x 2B
#define B_TILE  22528         // 176 rows x 64 bf16 x 2B
#define NT_     512

__device__ float g_z[(size_t)B_ * NCH_ * NSP_];
__device__ __nv_bfloat16 g_wprep[(size_t)NCHUNK_ * 2 * CO_ * KC_];  // pre-swizzled

// ---- smem byte offsets (dynamic smem) ----
#define SA_OFF    0            // A: [buf][hi,lo]  4 * 16384 = 65536
#define SB_OFF    65536        // B: [buf][hi,lo]  4 * 22528 = 90112 -> 155648
#define SX_OFF    155648       // xs: 1584 floats (incl 144-zero tail)
#define XS_FLOATS 1584
#define ST_OFF    161984       // tapoff table: 128 ints
#define SSB_OFF   162496       // scalar_bias 16 f
#define SGB_OFF   162560       // gate_bias 32 f
#define SMEM_TOTAL 162816

// ---------------- helpers ----------------
__device__ __forceinline__ uint32_t smem_u32(const void* p){
    uint32_t a;
    asm("{ .reg .u64 t; cvta.to.shared.u64 t, %1; cvt.u32.u64 %0, t; }"
        : "=r"(a) : "l"(p));
    return a;
}
__device__ __forceinline__ uint32_t swz(uint32_t o){
    return o ^ (((o >> 7) & 7u) << 4);
}

#define CPA16(d,s) asm volatile("cp.async.cg.shared.global [%0], [%1], 16;" :: "r"(d), "l"(s))
#define CPA8(d,s)  asm volatile("cp.async.ca.shared.global [%0], [%1], 8;"  :: "r"(d), "l"(s))
#define CPC()      asm volatile("cp.async.commit_group;")
#define CPW0()     asm volatile("cp.async.wait_group 0;")

#define LDM4(r, a) \
    asm volatile("ldmatrix.sync.aligned.m8n8.x4.shared.b16 {%0,%1,%2,%3}, [%4];" \
        : "=r"((r)[0]),"=r"((r)[1]),"=r"((r)[2]),"=r"((r)[3]) : "r"(a))
#define LDM2(r, a) \
    asm volatile("ldmatrix.sync.aligned.m8n8.x2.shared.b16 {%0,%1}, [%2];" \
        : "=r"((r)[0]),"=r"((r)[1]) : "r"(a))

#define MMA16816(d, a, b0v, b1v) \
    asm volatile("mma.sync.aligned.m16n8k16.row.col.f32.bf16.bf16.f32 " \
        "{%0,%1,%2,%3}, {%4,%5,%6,%7}, {%8,%9}, {%0,%1,%2,%3};" \
        : "+f"((d)[0]),"+f"((d)[1]),"+f"((d)[2]),"+f"((d)[3]) \
        : "r"((a)[0]),"r"((a)[1]),"r"((a)[2]),"r"((a)[3]), "r"(b0v), "r"(b1v))

// ---------------------------------------------------------------------------
// Weight prep: reorder to K=(ci*128+tap), split bf16 hi/lo, pre-apply the
// XOR swizzle so the main kernel can cp.async the tiles linearly.
// ---------------------------------------------------------------------------
__global__ void prep_kernel(const float* __restrict__ W)
{
    int e = blockIdx.x * 256 + threadIdx.x;   // 144*176*64 = 1,622,016 exact
    int col   = e & 63;
    int row   = (e >> 6) % CO_;
    int chunk = e / (CO_ * KC_);
    int k  = chunk * KC_ + col;
    int ci = k >> 7;
    int tap = k & 127;
    float v = (tap < 125) ? W[((size_t)row * CI_ + ci) * 125 + tap] : 0.f;
    __nv_bfloat16 hi = __float2bfloat16(v);
    __nv_bfloat16 lo = __float2bfloat16(v - __bfloat162float(hi));
    uint32_t off = (uint32_t)(row * 128 + col * 2);
    uint32_t sw  = off ^ ((uint32_t)(row & 7) << 4);
    size_t base = (size_t)chunk * 2 * (CO_ * KC_);
    g_wprep[base + (sw >> 1)]             = hi;
    g_wprep[base + CO_ * KC_ + (sw >> 1)] = lo;
}

// ---------------------------------------------------------------------------
// Main kernel: implicit GEMM + fused gate epilogue.
// grid (8 y-tiles, 32 z, 4 b), 512 threads. M-tile = 4y x 32x at fixed z.
// warps: 8M x 2N, warp tile M=16, N=88.
// ---------------------------------------------------------------------------
__global__ __launch_bounds__(NT_, 1)
void conv_mma_kernel(const float* __restrict__ x,
                     const float* __restrict__ sbg, const float* __restrict__ gbg)
{
    extern __shared__ unsigned char smem[];
    const uint32_t smb = smem_u32(smem);

    const int tid = threadIdx.x;
    const int wid = tid >> 5;
    const int lid = tid & 31;
    const int b  = blockIdx.z;
    const int z0 = blockIdx.y;
    const int y0 = blockIdx.x * 4;

    // builder role: 16 warps = 4 y-groups x 4 k-quarters
    const int byy = wid & 3, bkq = wid >> 2;
    // mma role: 8 M-groups x 2 N-halves
    const int m0 = (wid >> 1) * 16;
    const int n0 = (wid & 1) * 88;

    float* xs     = (float*)(smem + SX_OFF);
    int*   tapoff = (int*)(smem + ST_OFF);
    float* sS     = (float*)(smem + SSB_OFF);
    float* sG     = (float*)(smem + SGB_OFF);

    for (int i = tid; i < XS_FLOATS; i += NT_) xs[i] = 0.f;
    if (tid < 128) {
        int tap = tid;
        int kd = tap / 25, r = tap % 25;
        int kh = r / 5, kw = r % 5;
        tapoff[tid] = (tap < 125) ? (kd * 8 + kh) * 36 + kw : 1440;
    }
    if (tid < 16) sS[tid] = sbg[tid];
    if (tid < 32) sG[tid] = gbg[tid];
    __syncthreads();

    const float* xb = x + (size_t)b * CI_ * NSP_;

    auto stage_x = [&](int ci) {
        const float* xc = xb + (size_t)ci * NSP_;
        for (int it = tid; it < 640; it += NT_) {
            int ck = it & 15;
            int row = it >> 4;           // zi*8 + yi
            int yi = row & 7, zi = row >> 3;
            int gy = y0 + yi - 2, gz = z0 + zi - 2;
            if ((unsigned)gy < 32u && (unsigned)gz < 32u)
                CPA8(smb + SX_OFF + (uint32_t)(row * 36 + 2 + ck * 2) * 4,
                     xc + ((gz * 32 + gy) * 32 + ck * 2));
        }
    };
    auto stage_B = [&](int n, int nb) {
        const char* src = (const char*)g_wprep + (size_t)n * (2 * B_TILE);
        uint32_t dst = smb + SB_OFF + nb * (2 * B_TILE);
        for (int i = tid; i < (2 * B_TILE) / 16; i += NT_)
            CPA16(dst + i * 16, src + i * 16);
    };
    auto build_A = [&](int n, int nb) {
        char* Ah = (char*)smem + SA_OFF + nb * (2 * A_TILE);
        char* Al = Ah + A_TILE;
        const int tb  = (n & 1) * 64;
        const int lin = byy * 36 + lid;
        const int m   = byy * 32 + lid;
        const uint32_t mx = (uint32_t)(m & 7) << 4;
#pragma unroll
        for (int j = 0; j < 8; ++j) {
            int k0 = bkq * 16 + 2 * j;
            float v0 = xs[tapoff[tb + k0]     + lin];
            float v1 = xs[tapoff[tb + k0 + 1] + lin];
            __nv_bfloat16 h0 = __float2bfloat16(v0);
            __nv_bfloat16 h1 = __float2bfloat16(v1);
            __nv_bfloat16 l0 = __float2bfloat16(v0 - __bfloat162float(h0));
            __nv_bfloat16 l1 = __float2bfloat16(v1 - __bfloat162float(h1));
            uint32_t hp = (uint32_t)__bfloat16_as_ushort(h0) |
                          ((uint32_t)__bfloat16_as_ushort(h1) << 16);
            uint32_t lp = (uint32_t)__bfloat16_as_ushort(l0) |
                          ((uint32_t)__bfloat16_as_ushort(l1) << 16);
            uint32_t sw = ((uint32_t)(m * 128 + k0 * 2)) ^ mx;
            *(uint32_t*)(Ah + sw) = hp;
            *(uint32_t*)(Al + sw) = lp;
        }
    };

    // lane-invariant ldmatrix offsets
    const uint32_t aLane  = (uint32_t)((lid & 15) * 128 + ((lid & 16) ? 16 : 0));
    const uint32_t bLane4 = (uint32_t)((((lid & 7) + ((lid & 16) ? 8 : 0)) * 128) +
                                       ((lid & 8) ? 16 : 0));
    const uint32_t bLane2 = (uint32_t)((lid & 7) * 128 + ((lid & 8) ? 16 : 0));

    float acc[11][4];
#pragma unroll
    for (int ni = 0; ni < 11; ++ni)
#pragma unroll
        for (int r = 0; r < 4; ++r) acc[ni][r] = 0.f;

    // ---- prologue ----
    stage_B(0, 0);
    stage_x(0);
    CPC(); CPW0();
    __syncthreads();
    build_A(0, 0);
    __syncthreads();

    for (int c = 0; c < NCHUNK_; ++c) {
        const int bsel = c & 1;
        if (c + 1 < NCHUNK_) {
            stage_B(c + 1, bsel ^ 1);
            if (((c + 1) & 1) == 0) stage_x((c + 1) >> 1);
            CPC();
        }

        const uint32_t AhB = smb + SA_OFF + bsel * (2 * A_TILE);
        const uint32_t AlB = AhB + A_TILE;
        const uint32_t BhB = smb + SB_OFF + bsel * (2 * B_TILE);
        const uint32_t BlB = BhB + B_TILE;

#pragma unroll
        for (int ks = 0; ks < 4; ++ks) {
            const uint32_t kso = (uint32_t)ks * 32;
            uint32_t ah[4], al[4];
            LDM4(ah, AhB + swz((uint32_t)(m0 * 128) + kso + aLane));
            LDM4(al, AlB + swz((uint32_t)(m0 * 128) + kso + aLane));
#pragma unroll
            for (int nip = 0; nip < 5; ++nip) {
                uint32_t bh[4], bl[4];
                const uint32_t bo =
                    swz((uint32_t)((n0 + nip * 16) * 128) + kso + bLane4);
                LDM4(bh, BhB + bo);
                LDM4(bl, BlB + bo);
#pragma unroll
                for (int sub = 0; sub < 2; ++sub) {
                    const int ni = nip * 2 + sub;
                    MMA16816(acc[ni], ah, bh[sub*2], bh[sub*2+1]);
                    MMA16816(acc[ni], al, bh[sub*2], bh[sub*2+1]);
                    MMA16816(acc[ni], ah, bl[sub*2], bl[sub*2+1]);
                }
            }
            {   // n-group 10 (cols 80..87)
                uint32_t bh[2], bl[2];
                const uint32_t bo =
                    swz((uint32_t)((n0 + 80) * 128) + kso + bLane2);
                LDM2(bh, BhB + bo);
                LDM2(bl, BlB + bo);
                MMA16816(acc[10], ah, bh[0], bh[1]);
                MMA16816(acc[10], al, bh[0], bh[1]);
                MMA16816(acc[10], ah, bl[0], bl[1]);
            }
        }

        if (c + 1 < NCHUNK_) {
            CPW0();
            __syncthreads();
            build_A(c + 1, bsel ^ 1);
        }
        __syncthreads();
    }

    // ---- epilogue: accums -> smem, sigmoid gates, gated write to g_z ----
    float* sD = (float*)smem;   // [176][132] floats = 92928B, reuses tile smem
#pragma unroll
    for (int ni = 0; ni < 11; ++ni)
#pragma unroll
        for (int r = 0; r < 4; ++r) {
            int m  = m0 + (lid >> 2) + ((r & 2) ? 8 : 0);
            int cc = n0 + ni * 8 + (lid & 3) * 2 + (r & 1);
            sD[cc * 132 + m] = acc[ni][r];
        }
    __syncthreads();

    for (int i = tid; i < 32 * 128; i += NT_) {
        int gi = i >> 7, mm = i & 127;
        int ad = (144 + gi) * 132 + mm;
        sD[ad] = 1.f / (1.f + expf(-(sD[ad] + sG[gi])));
    }
    __syncthreads();

    float* zb = g_z + (size_t)b * NCH_ * NSP_ + (size_t)z0 * 1024 + y0 * 32;
    for (int i = tid; i < 144 * 128; i += NT_) {
        int cc = i >> 7, mm = i & 127;
        float v = sD[cc * 132 + mm];
        float o;
        if (cc < 16) o = fmaxf(v + sS[cc], 0.f);
        else {
            int gi = (cc < 64) ? (cc - 16) / 3 : 16 + (cc - 64) / 5;
            o = v * sD[(144 + gi) * 132 + mm];
        }
        zb[(size_t)cc * NSP_ + mm] = o;
    }
}

// ---------------------------------------------------------------------------
// Depthwise 5^3 gaussian, stride2, pad2 -> (16,16,16). grid (8, 144, 4).
// ---------------------------------------------------------------------------
__global__ __launch_bounds__(256)
void lowpass_kernel(float* __restrict__ out)
{
    const int zt = blockIdx.x;
    const int c  = blockIdx.y;
    const int b  = blockIdx.z;
    const int tid = threadIdx.x;

    __shared__ float sZ[7 * 35 * 35];
    __shared__ float sWg[125];

    if (tid < 125) {
        int kw = tid % 5, t = tid / 5;
        int kh = t % 5,  kd = t / 5;
        double g[5], s = 0.0;
#pragma unroll
        for (int r = 0; r < 5; ++r) {
            double d = (double)(r - 2);
            g[r] = exp(-d * d / 1.5);
            s += g[r];
        }
        sWg[tid] = (float)(g[kd] * g[kh] * g[kw] / (s * s * s));
    }

    const int zo0 = 2 * zt;
    const int zi0 = 2 * zo0 - 2;
    const float* zc = g_z + (size_t)(b * NCH_ + c) * NSP_;

    for (int i = tid; i < 7 * 35 * 35; i += 256) {
        int xi = i % 35;
        int t  = i / 35;
        int yi = t % 35;
        int zi = t / 35;
        int gx = xi - 2, gy = yi - 2, gz = zi0 + zi;
        float v = 0.f;
        if ((unsigned)gx < 32u && (unsigned)gy < 32u && (unsigned)gz < 32u)
            v = zc[(gz * 32 + gy) * 32 + gx];
        sZ[i] = v;
    }
    __syncthreads();

    const int xo = tid & 15;
    const int yo = tid >> 4;
#pragma unroll
    for (int dz = 0; dz < 2; ++dz) {
        float sum = 0.f;
#pragma unroll
        for (int kd = 0; kd < 5; ++kd)
#pragma unroll
            for (int kh = 0; kh < 5; ++kh)
#pragma unroll
                for (int kw = 0; kw < 5; ++kw)
                    sum += sWg[(kd * 5 + kh) * 5 + kw] *
                           sZ[((2 * dz + kd) * 35 + (2 * yo + kh)) * 35 +
                              2 * xo + kw];
        out[((size_t)(b * NCH_ + c) * 16 + (zo0 + dz)) * 256 + yo * 16 + xo] = sum;
    }
}

// ---------------------------------------------------------------------------
extern "C" void kernel_launch(void* const* d_in, const int* in_sizes, int n_in,
                              void* d_out, int out_size)
{
    const float* x  = (const float*)d_in[0];   // (4,72,32,32,32)
    const float* W  = (const float*)d_in[1];   // (176,72,5,5,5)
    const float* sb = (const float*)d_in[2];   // (16,)
    const float* gb = (const float*)d_in[3];   // (32,)
    float* out = (float*)d_out;                // (4,144,16,16,16)

    cudaFuncSetAttribute(conv_mma_kernel,
                         cudaFuncAttributeMaxDynamicSharedMemorySize, SMEM_TOTAL);

    prep_kernel<<<6336, 256>>>(W);
    conv_mma_kernel<<<dim3(8, 32, B_), NT_, SMEM_TOTAL>>>(x, sb, gb);
    lowpass_kernel<<<dim3(8, NCH_, B_), 256>>>(out);
}